// round 7
// baseline (speedup 1.0000x reference)
#include <cuda_runtime.h>
#include <stdint.h>

// Problem constants
#define NB   8
#define CIN  3
#define HW   128
#define OC   16
#define NF   27          // Cin*3*3

// Device scratch: two half-tables, 16B rows (8 channels each).
__device__ __align__(16) short g_prodA[NF*256*8];   // [f][ip][o:0-7]   108KB
__device__ __align__(16) short g_prodB[NF*256*8];   // [f][ip][o:8-15]  108KB

// ---------------------------------------------------------------------------
// Table builder: one thread per (f, ip, o). Quantizes its weight inline,
// gathers lut pair, writes combined int16 product into the split tables.
// ---------------------------------------------------------------------------
__global__ void prep_table(const float* __restrict__ w,
                           const float* __restrict__ swp,
                           const int*   __restrict__ lut)
{
    int idx = blockIdx.x * blockDim.x + threadIdx.x;   // 27*256*16 = 110592
    if (idx >= NF*256*OC) return;
    int o  = idx & 15;
    int ip = (idx >> 4) & 255;
    int f  = idx >> 12;

    float q = rintf(w[o*NF + f] / swp[0]);   // round-half-even like jnp.round
    q = fminf(fmaxf(q, -127.0f), 127.0f);
    int iw = (int)q + 128;

    int row = ip*256 + iw;
    int2 hl = ((const int2*)lut)[row];       // (hi, lo)
    short v = (short)(hl.x*256 + (hl.y & 255));

    if (o < 8) g_prodA[(f*256 + ip)*8 + o]     = v;
    else       g_prodB[(f*256 + ip)*8 + (o-8)] = v;
}

// ---------------------------------------------------------------------------
// Conv: 256 blocks x 1024 threads, TWO blocks per SM (channel halves).
// Each block: one 108KB half-table + 3.9KB tile in SMEM, 8 output channels.
// Inner loop: per tap 1x LDS.128 + 8x dp2a (single-instruction halfword
// accumulate) -> minimal instructions, ~25 live regs -> MLP within 32-reg cap.
// ---------------------------------------------------------------------------
#define SM_A_BYTES    (NF*256*8*2)              // 110592
#define SM_TILE_BYTES ((3*10*130 + 15) & ~15)   // 3904
#define SM_TOTAL      (SM_A_BYTES + SM_TILE_BYTES)

__global__ __launch_bounds__(1024, 2)
void conv_kernel(const float* __restrict__ x,
                 const float* __restrict__ bias,
                 const float* __restrict__ sxp,
                 const float* __restrict__ swp,
                 float* __restrict__ out)
{
    extern __shared__ char smem[];
    unsigned char* stile = (unsigned char*)(smem + SM_A_BYTES);

    const int tid  = threadIdx.x;
    const int half = blockIdx.x & 1;          // channel half: 0 -> o 0-7, 1 -> o 8-15
    const int rest = blockIdx.x >> 1;
    const int b    = rest >> 4;               // batch
    const int rowg = rest & 15;               // 8-row group within image

    // Stage this block's 108KB half-table (int4 vector copies)
    {
        const int4* src = half ? (const int4*)g_prodB : (const int4*)g_prodA;
        int4* dst = (int4*)smem;
        #pragma unroll
        for (int k = 0; k < 6; k++)
            dst[tid + k*1024] = src[tid + k*1024];
        if (tid < (SM_A_BYTES/16 - 6*1024))   // 768 remaining
            dst[tid + 6*1024] = src[tid + 6*1024];
    }

    // Stage + quantize activation tile [3][10][130]; out-of-image -> ip=128
    {
        const float sx = sxp[0];
        for (int t = tid; t < 3*10*130; t += 1024) {
            int cin = t / 1300;
            int rem = t - cin*1300;
            int rr  = rem / 130;
            int cc  = rem - rr*130;
            int hh  = rowg*8 + rr - 1;
            int ww  = cc - 1;
            unsigned char v = 128;
            if ((unsigned)hh < 128u && (unsigned)ww < 128u) {
                float xf = x[((b*3 + cin)*128 + hh)*128 + ww];
                float q = rintf(xf / sx);                 // round-half-even
                q = fminf(fmaxf(q, -127.0f), 127.0f);
                v = (unsigned char)((int)q + 128);
            }
            stile[t] = v;
        }
    }
    __syncthreads();

    const int c = tid & 127;   // column
    const int r = tid >> 7;    // row within 8-row group

    int acc[8];
    #pragma unroll
    for (int o = 0; o < 8; o++) acc[o] = 0;

    const uint4* TA = (const uint4*)smem;
    const unsigned char* tb = &stile[r*130 + c];

    #pragma unroll 1
    for (int cin = 0; cin < 3; cin++) {
        // Load all 9 tile bytes for this input channel first (independent LDS)
        int ipx[9];
        #pragma unroll
        for (int dh = 0; dh < 3; dh++)
            #pragma unroll
            for (int dw = 0; dw < 3; dw++)
                ipx[dh*3 + dw] = (int)tb[cin*1300 + dh*130 + dw];

        // 9 straight-line taps; 1 LDS.128 + 8 dp2a each
        #pragma unroll
        for (int t = 0; t < 9; t++) {
            uint4 v = TA[(cin*9 + t)*256 + ipx[t]];
            acc[0] = __dp2a_lo((int)v.x, 0x0001, acc[0]);   // += h0(v.x)
            acc[1] = __dp2a_lo((int)v.x, 0x0100, acc[1]);   // += h1(v.x)
            acc[2] = __dp2a_lo((int)v.y, 0x0001, acc[2]);
            acc[3] = __dp2a_lo((int)v.y, 0x0100, acc[3]);
            acc[4] = __dp2a_lo((int)v.z, 0x0001, acc[4]);
            acc[5] = __dp2a_lo((int)v.z, 0x0100, acc[5]);
            acc[6] = __dp2a_lo((int)v.w, 0x0001, acc[6]);
            acc[7] = __dp2a_lo((int)v.w, 0x0100, acc[7]);
        }
    }

    const float s = sxp[0] * swp[0];
    const int h = rowg*8 + r;
    float* obase = &out[((b*OC + half*8)*128 + h)*128 + c];
    #pragma unroll
    for (int o = 0; o < 8; o++)
        obase[o*128*128] = (float)acc[o] * s + __ldg(&bias[half*8 + o]);
}

// ---------------------------------------------------------------------------
extern "C" void kernel_launch(void* const* d_in, const int* in_sizes, int n_in,
                              void* d_out, int out_size)
{
    const float* x    = (const float*)d_in[0];
    const float* w    = (const float*)d_in[1];
    const float* bias = (const float*)d_in[2];
    const float* sx   = (const float*)d_in[3];
    const float* sw   = (const float*)d_in[4];
    const int*   lut  = (const int*)d_in[5];
    float* out = (float*)d_out;

    cudaFuncSetAttribute(conv_kernel,
                         cudaFuncAttributeMaxDynamicSharedMemorySize, SM_TOTAL);

    prep_table<<<(NF*256*OC + 255) / 256, 256>>>(w, sw, lut);
    conv_kernel<<<NB * 16 * 2, 1024, SM_TOTAL>>>(x, bias, sx, sw, out);
}

// round 8
// speedup vs baseline: 1.0014x; 1.0014x over previous
#include <cuda_runtime.h>
#include <stdint.h>

// Problem constants
#define NB   8
#define CIN  3
#define HW   128
#define OC   16
#define NF   27          // Cin*3*3

// Device scratch: two half-tables, 16B rows (8 channels each).
__device__ __align__(16) short g_prodA[NF*256*8];   // [f][ip][o:0-7]   108KB
__device__ __align__(16) short g_prodB[NF*256*8];   // [f][ip][o:8-15]  108KB

// ---------------------------------------------------------------------------
// Table builder: one thread per (f, ip, o).
// ---------------------------------------------------------------------------
__global__ void prep_table(const float* __restrict__ w,
                           const float* __restrict__ swp,
                           const int*   __restrict__ lut)
{
    int idx = blockIdx.x * blockDim.x + threadIdx.x;   // 27*256*16 = 110592
    if (idx >= NF*256*OC) return;
    int o  = idx & 15;
    int ip = (idx >> 4) & 255;
    int f  = idx >> 12;

    float q = rintf(w[o*NF + f] / swp[0]);   // round-half-even like jnp.round
    q = fminf(fmaxf(q, -127.0f), 127.0f);
    int iw = (int)q + 128;

    int row = ip*256 + iw;
    int2 hl = ((const int2*)lut)[row];       // (hi, lo)
    short v = (short)(hl.x*256 + (hl.y & 255));

    if (o < 8) g_prodA[(f*256 + ip)*8 + o]     = v;
    else       g_prodB[(f*256 + ip)*8 + (o-8)] = v;
}

// ---------------------------------------------------------------------------
// Conv: 256 blocks x 1024 threads, 2 blocks/SM (channel halves).
// Mainloop: per dh-row batch of 3 table LDS.128 + next-row byte prefetch
// (6 memory ops in flight over 24 dp2a), warp-staggered cin start phase.
// ---------------------------------------------------------------------------
#define SM_A_BYTES    (NF*256*8*2)              // 110592
#define SM_TILE_BYTES ((3*10*130 + 15) & ~15)   // 3904
#define SM_TOTAL      (SM_A_BYTES + SM_TILE_BYTES)

__global__ __launch_bounds__(1024, 2)
void conv_kernel(const float* __restrict__ x,
                 const float* __restrict__ bias,
                 const float* __restrict__ sxp,
                 const float* __restrict__ swp,
                 float* __restrict__ out)
{
    extern __shared__ char smem[];
    unsigned char* stile = (unsigned char*)(smem + SM_A_BYTES);

    const int tid  = threadIdx.x;
    const int half = blockIdx.x & 1;          // channel half: 0 -> o 0-7, 1 -> o 8-15
    const int rest = blockIdx.x >> 1;
    const int b    = rest >> 4;               // batch
    const int rowg = rest & 15;               // 8-row group within image

    // Stage this block's 108KB half-table (int4 vector copies)
    {
        const int4* src = half ? (const int4*)g_prodB : (const int4*)g_prodA;
        int4* dst = (int4*)smem;
        #pragma unroll
        for (int k = 0; k < 6; k++)
            dst[tid + k*1024] = src[tid + k*1024];
        if (tid < (SM_A_BYTES/16 - 6*1024))   // 768 remaining
            dst[tid + 6*1024] = src[tid + 6*1024];
    }

    // Stage + quantize activation tile [3][10][130]; out-of-image -> ip=128
    {
        const float sx = sxp[0];
        for (int t = tid; t < 3*10*130; t += 1024) {
            int cin = t / 1300;
            int rem = t - cin*1300;
            int rr  = rem / 130;
            int cc  = rem - rr*130;
            int hh  = rowg*8 + rr - 1;
            int ww  = cc - 1;
            unsigned char v = 128;
            if ((unsigned)hh < 128u && (unsigned)ww < 128u) {
                float xf = x[((b*3 + cin)*128 + hh)*128 + ww];
                float q = rintf(xf / sx);                 // round-half-even
                q = fminf(fmaxf(q, -127.0f), 127.0f);
                v = (unsigned char)((int)q + 128);
            }
            stile[t] = v;
        }
    }
    __syncthreads();

    const int c = tid & 127;   // column
    const int r = tid >> 7;    // row within 8-row group

    int acc[8];
    #pragma unroll
    for (int o = 0; o < 8; o++) acc[o] = 0;

    const uint4* TA = (const uint4*)smem;
    const unsigned char* tb = &stile[r*130 + c];

    // Warp-staggered cin phase: warp w starts at cin = w % 3 (sum commutes)
    int cin = (tid >> 5) % 3;

    #pragma unroll 1
    for (int phase = 0; phase < 3; phase++) {
        const uint4* Tc = TA + cin*(9*256);              // this cin's 9-tap table
        const unsigned char* tbc = tb + cin*1300;

        // Prime: dh=0 row bytes
        int ip0 = (int)tbc[0*130 + 0];
        int ip1 = (int)tbc[0*130 + 1];
        int ip2 = (int)tbc[0*130 + 2];

        #pragma unroll
        for (int dh = 0; dh < 3; dh++) {
            // Issue the 3 table loads for this row (independent LDS.128s)
            uint4 v0 = Tc[(dh*3 + 0)*256 + ip0];
            uint4 v1 = Tc[(dh*3 + 1)*256 + ip1];
            uint4 v2 = Tc[(dh*3 + 2)*256 + ip2];

            // Prefetch next row's bytes while the table loads are in flight
            if (dh < 2) {
                ip0 = (int)tbc[(dh+1)*130 + 0];
                ip1 = (int)tbc[(dh+1)*130 + 1];
                ip2 = (int)tbc[(dh+1)*130 + 2];
            }

            acc[0] = __dp2a_lo((int)v0.x, 0x0001, acc[0]);
            acc[1] = __dp2a_lo((int)v0.x, 0x0100, acc[1]);
            acc[2] = __dp2a_lo((int)v0.y, 0x0001, acc[2]);
            acc[3] = __dp2a_lo((int)v0.y, 0x0100, acc[3]);
            acc[4] = __dp2a_lo((int)v0.z, 0x0001, acc[4]);
            acc[5] = __dp2a_lo((int)v0.z, 0x0100, acc[5]);
            acc[6] = __dp2a_lo((int)v0.w, 0x0001, acc[6]);
            acc[7] = __dp2a_lo((int)v0.w, 0x0100, acc[7]);

            acc[0] = __dp2a_lo((int)v1.x, 0x0001, acc[0]);
            acc[1] = __dp2a_lo((int)v1.x, 0x0100, acc[1]);
            acc[2] = __dp2a_lo((int)v1.y, 0x0001, acc[2]);
            acc[3] = __dp2a_lo((int)v1.y, 0x0100, acc[3]);
            acc[4] = __dp2a_lo((int)v1.z, 0x0001, acc[4]);
            acc[5] = __dp2a_lo((int)v1.z, 0x0100, acc[5]);
            acc[6] = __dp2a_lo((int)v1.w, 0x0001, acc[6]);
            acc[7] = __dp2a_lo((int)v1.w, 0x0100, acc[7]);

            acc[0] = __dp2a_lo((int)v2.x, 0x0001, acc[0]);
            acc[1] = __dp2a_lo((int)v2.x, 0x0100, acc[1]);
            acc[2] = __dp2a_lo((int)v2.y, 0x0001, acc[2]);
            acc[3] = __dp2a_lo((int)v2.y, 0x0100, acc[3]);
            acc[4] = __dp2a_lo((int)v2.z, 0x0001, acc[4]);
            acc[5] = __dp2a_lo((int)v2.z, 0x0100, acc[5]);
            acc[6] = __dp2a_lo((int)v2.w, 0x0001, acc[6]);
            acc[7] = __dp2a_lo((int)v2.w, 0x0100, acc[7]);
        }

        cin = (cin == 2) ? 0 : cin + 1;
    }

    const float s = sxp[0] * swp[0];
    const int h = rowg*8 + r;
    float* obase = &out[((b*OC + half*8)*128 + h)*128 + c];
    #pragma unroll
    for (int o = 0; o < 8; o++)
        obase[o*128*128] = (float)acc[o] * s + __ldg(&bias[half*8 + o]);
}

// ---------------------------------------------------------------------------
extern "C" void kernel_launch(void* const* d_in, const int* in_sizes, int n_in,
                              void* d_out, int out_size)
{
    const float* x    = (const float*)d_in[0];
    const float* w    = (const float*)d_in[1];
    const float* bias = (const float*)d_in[2];
    const float* sx   = (const float*)d_in[3];
    const float* sw   = (const float*)d_in[4];
    const int*   lut  = (const int*)d_in[5];
    float* out = (float*)d_out;

    cudaFuncSetAttribute(conv_kernel,
                         cudaFuncAttributeMaxDynamicSharedMemorySize, SM_TOTAL);

    prep_table<<<(NF*256*OC + 255) / 256, 256>>>(w, sw, lut);
    conv_kernel<<<NB * 16 * 2, 1024, SM_TOTAL>>>(x, bias, sx, sw, out);
}

// round 9
// speedup vs baseline: 1.0992x; 1.0977x over previous
#include <cuda_runtime.h>
#include <stdint.h>

// Problem constants
#define NB   8
#define CIN  3
#define HW   128
#define OC   16
#define NF   27          // Cin*3*3

// Device scratch: two half-tables, 16B rows (8 channels each).
__device__ __align__(16) short g_prodA[NF*256*8];   // [f][ip][o:0-7]   108KB
__device__ __align__(16) short g_prodB[NF*256*8];   // [f][ip][o:8-15]  108KB

// ---------------------------------------------------------------------------
// Table builder: one thread per (f, ip, o).
// ---------------------------------------------------------------------------
__global__ void prep_table(const float* __restrict__ w,
                           const float* __restrict__ swp,
                           const int*   __restrict__ lut)
{
    int idx = blockIdx.x * blockDim.x + threadIdx.x;   // 27*256*16 = 110592
    if (idx >= NF*256*OC) return;
    int o  = idx & 15;
    int ip = (idx >> 4) & 255;
    int f  = idx >> 12;

    float q = rintf(w[o*NF + f] / swp[0]);   // round-half-even like jnp.round
    q = fminf(fmaxf(q, -127.0f), 127.0f);
    int iw = (int)q + 128;

    int row = ip*256 + iw;
    int2 hl = ((const int2*)lut)[row];       // (hi, lo)
    short v = (short)(hl.x*256 + (hl.y & 255));

    if (o < 8) g_prodA[(f*256 + ip)*8 + o]     = v;
    else       g_prodB[(f*256 + ip)*8 + (o-8)] = v;
}

// ---------------------------------------------------------------------------
// Conv: 128 blocks x 1024 threads, ONE block per SM, 64-reg budget.
// Both half-tables in SMEM (216KB). Mainloop: fully unrolled 27 taps with an
// explicit 4-slot circular register buffer -> 8 LDS.128 in flight per warp.
// Tap offsets are compile-time immediates (no indirection loads).
// ---------------------------------------------------------------------------
#define SM_A_BYTES    (NF*256*8*2)              // 110592
#define SM_AB_BYTES   (2*SM_A_BYTES)            // 221184
#define SM_TILE_BYTES ((3*10*130 + 15) & ~15)   // 3904
#define SM_TOTAL      (SM_AB_BYTES + SM_TILE_BYTES)   // 225088

__global__ __launch_bounds__(1024, 1)
void conv_kernel(const float* __restrict__ x,
                 const float* __restrict__ bias,
                 const float* __restrict__ sxp,
                 const float* __restrict__ swp,
                 float* __restrict__ out)
{
    extern __shared__ char smem[];
    unsigned char* stile = (unsigned char*)(smem + SM_AB_BYTES);

    const int tid  = threadIdx.x;
    const int b    = blockIdx.x >> 4;   // batch
    const int rowg = blockIdx.x & 15;   // 8-row group within image

    // Stage both half-tables (216KB) with int4 vector copies
    {
        const int4* srcA = (const int4*)g_prodA;
        const int4* srcB = (const int4*)g_prodB;
        int4* dstA = (int4*)smem;
        int4* dstB = (int4*)(smem + SM_A_BYTES);
        #pragma unroll
        for (int k = 0; k < 6; k++) {
            dstA[tid + k*1024] = srcA[tid + k*1024];
            dstB[tid + k*1024] = srcB[tid + k*1024];
        }
        if (tid < (SM_A_BYTES/16 - 6*1024)) {           // 768 remaining
            dstA[tid + 6*1024] = srcA[tid + 6*1024];
            dstB[tid + 6*1024] = srcB[tid + 6*1024];
        }
    }

    // Stage + quantize activation tile [3][10][130]; out-of-image -> ip=128
    {
        const float sx = sxp[0];
        for (int t = tid; t < 3*10*130; t += 1024) {
            int cin = t / 1300;
            int rem = t - cin*1300;
            int rr  = rem / 130;
            int cc  = rem - rr*130;
            int hh  = rowg*8 + rr - 1;
            int ww  = cc - 1;
            unsigned char v = 128;
            if ((unsigned)hh < 128u && (unsigned)ww < 128u) {
                float xf = x[((b*3 + cin)*128 + hh)*128 + ww];
                float q = rintf(xf / sx);                 // round-half-even
                q = fminf(fmaxf(q, -127.0f), 127.0f);
                v = (unsigned char)((int)q + 128);
            }
            stile[t] = v;
        }
    }
    __syncthreads();

    const int c = tid & 127;   // column
    const int r = tid >> 7;    // row within 8-row group

    int acc[OC];
    #pragma unroll
    for (int o = 0; o < OC; o++) acc[o] = 0;

    const uint4* TA = (const uint4*)smem;
    const uint4* TB = (const uint4*)(smem + SM_A_BYTES);
    const unsigned char* tb = &stile[r*130 + c];

    // Compile-time tap offsets into the tile: cin*1300 + dh*130 + dw
    #define TOFF(f) (((f)/9)*1300 + (((f)%9)/3)*130 + ((f)%3))

    // 4-deep circular register buffer: 8 LDS.128 in flight per warp
    uint4 bufA[4], bufB[4];
    #pragma unroll
    for (int j = 0; j < 4; j++) {
        const int ipj = (int)tb[TOFF(j)];
        bufA[j] = TA[j*256 + ipj];
        bufB[j] = TB[j*256 + ipj];
    }

    #pragma unroll
    for (int f = 0; f < 27; f++) {
        const int s = f & 3;
        uint4 va = bufA[s];
        uint4 vb = bufB[s];

        if (f + 4 < 27) {                       // refill slot s with tap f+4
            const int ipn = (int)tb[TOFF(f + 4)];
            bufA[s] = TA[(f + 4)*256 + ipn];
            bufB[s] = TB[(f + 4)*256 + ipn];
        }

        acc[ 0] = __dp2a_lo((int)va.x, 0x0001, acc[ 0]);
        acc[ 1] = __dp2a_lo((int)va.x, 0x0100, acc[ 1]);
        acc[ 2] = __dp2a_lo((int)va.y, 0x0001, acc[ 2]);
        acc[ 3] = __dp2a_lo((int)va.y, 0x0100, acc[ 3]);
        acc[ 4] = __dp2a_lo((int)va.z, 0x0001, acc[ 4]);
        acc[ 5] = __dp2a_lo((int)va.z, 0x0100, acc[ 5]);
        acc[ 6] = __dp2a_lo((int)va.w, 0x0001, acc[ 6]);
        acc[ 7] = __dp2a_lo((int)va.w, 0x0100, acc[ 7]);
        acc[ 8] = __dp2a_lo((int)vb.x, 0x0001, acc[ 8]);
        acc[ 9] = __dp2a_lo((int)vb.x, 0x0100, acc[ 9]);
        acc[10] = __dp2a_lo((int)vb.y, 0x0001, acc[10]);
        acc[11] = __dp2a_lo((int)vb.y, 0x0100, acc[11]);
        acc[12] = __dp2a_lo((int)vb.z, 0x0001, acc[12]);
        acc[13] = __dp2a_lo((int)vb.z, 0x0100, acc[13]);
        acc[14] = __dp2a_lo((int)vb.w, 0x0001, acc[14]);
        acc[15] = __dp2a_lo((int)vb.w, 0x0100, acc[15]);

        // Bound instruction motion: keep the pipeline window at 4 taps
        asm volatile("" ::: "memory");
    }

    const float s = sxp[0] * swp[0];
    const int h = rowg*8 + r;
    float* obase = &out[(b*OC*128 + h)*128 + c];
    #pragma unroll
    for (int o = 0; o < OC; o++)
        obase[o*128*128] = (float)acc[o] * s + __ldg(&bias[o]);
}

// ---------------------------------------------------------------------------
extern "C" void kernel_launch(void* const* d_in, const int* in_sizes, int n_in,
                              void* d_out, int out_size)
{
    const float* x    = (const float*)d_in[0];
    const float* w    = (const float*)d_in[1];
    const float* bias = (const float*)d_in[2];
    const float* sx   = (const float*)d_in[3];
    const float* sw   = (const float*)d_in[4];
    const int*   lut  = (const int*)d_in[5];
    float* out = (float*)d_out;

    cudaFuncSetAttribute(conv_kernel,
                         cudaFuncAttributeMaxDynamicSharedMemorySize, SM_TOTAL);

    prep_table<<<(NF*256*OC + 255) / 256, 256>>>(w, sw, lut);
    conv_kernel<<<NB * 16, 1024, SM_TOTAL>>>(x, bias, sx, sw, out);
}